// round 15
// baseline (speedup 1.0000x reference)
#include <cuda_runtime.h>
#include <cuda_bf16.h>
#include <cstdint>
#include <math.h>

// CapacityAwareRouter: x(8192,2048) @ W(64,2048)^T + bias -> greedy capacity routing
#define N_TOK   8192
#define N_EXP   64
#define DIM     2048
#define TOPK    4
#define OUT_W_OFF (N_TOK * TOPK)
#define CAND_MAX 8
#define MARGIN  0.06f

// kernel A: 256 worker blocks + 1 spinner; 256 threads; 32 tokens/block
#define MT       32
#define NWORK    (N_TOK / MT)        // 256
#define KC       64                  // bf16 K elems per chunk
#define NCHUNK   (DIM / KC)          // 32
#define L_STRIDE  65
#define XBYTES   (MT * 72 * 2)       // 4608
#define WBYTES   (N_EXP * 72 * 2)    // 9216

// ---------------- device scratch ----------------
__device__ float g_logits[N_TOK * N_EXP];                    // fallback only
__device__ int   g_count[N_EXP];
__device__ int   g_done;
__device__ __align__(16) __nv_bfloat16 g_wbf[N_EXP * DIM];   // 256 KB bf16 W

__device__ __forceinline__ uint32_t bf2(float lo, float hi) {
    uint32_t r;
    asm("cvt.rn.bf16x2.f32 %0, %2, %1;" : "=r"(r) : "f"(lo), "f"(hi));
    return r;
}
#define CP16(dst, src) \
    asm volatile("cp.async.cg.shared.global [%0], [%1], 16;" :: "r"(dst), "l"(src) : "memory")
#define CP_COMMIT() asm volatile("cp.async.commit_group;" ::: "memory")
#define CP_WAIT0()  asm volatile("cp.async.wait_group 0;" ::: "memory")

// ============ kernel W: fp32 W -> bf16 global ============
__global__ void wconv_kernel(const float* __restrict__ W) {
    const int i = (blockIdx.x * 256 + threadIdx.x) * 8;
    float4 a = *(const float4*)(W + i);
    float4 b = *(const float4*)(W + i + 4);
    uint4 v;
    v.x = bf2(a.x, a.y); v.y = bf2(a.z, a.w);
    v.z = bf2(b.x, b.y); v.w = bf2(b.z, b.w);
    *(uint4*)(g_wbf + i) = v;
}

// ============ kernel A: GEMM + routing + integrated fallback spinner ============
__global__ __launch_bounds__(256, 2)
void gemm_route_kernel(const float* __restrict__ x, const float* __restrict__ Wt,
                       const float* __restrict__ bias, const int* __restrict__ tc,
                       float* __restrict__ out) {
    __shared__ __align__(16) char smx[2 * XBYTES];   // x tiles (logits overlay later)
    __shared__ __align__(16) char smw[2 * WBYTES];   // W tiles
    __shared__ float s_bias[N_EXP];
    __shared__ int   s_cnt[N_EXP];
    __shared__ int   s_queue[MT];
    __shared__ int   s_nc[MT];
    __shared__ int   s_cand[MT][CAND_MAX];
    __shared__ int   s_qn;
    __shared__ int   s_bad;

    const int tid  = threadIdx.x;
    const int wid  = tid >> 5;
    const int lane = tid & 31;

    // ================= spinner block: capacity check + exact fallback =================
    if (blockIdx.x == NWORK) {
        if (tid == 0) {
            while (atomicAdd(&g_done, 0) < NWORK) { __nanosleep(200); }
            s_bad = 0;
        }
        __syncthreads();
        const int cap = tc[0] / TOPK;
        if (tid < N_EXP && TOPK * g_count[tid] > cap) atomicOr(&s_bad, 1);
        __syncthreads();
        const int bad = s_bad;
        if (tid < N_EXP) g_count[tid] = 0;   // reset for next replay
        if (tid == 0) g_done = 0;
        if (!bad) return;

        // ---- never-taken exact path: full fp32 logits + serial greedy ----
        for (int p = tid; p < N_TOK * N_EXP; p += 256) {
            const int b = p >> 6, e = p & 63;
            const float4* xr = (const float4*)(x + (size_t)b * DIM);
            const float4* wr = (const float4*)(Wt + (size_t)e * DIM);
            float acc = 0.f;
            for (int i = 0; i < DIM / 4; i++) {
                float4 a = xr[i], cc = wr[i];
                acc = fmaf(a.x, cc.x, acc); acc = fmaf(a.y, cc.y, acc);
                acc = fmaf(a.z, cc.z, acc); acc = fmaf(a.w, cc.w, acc);
            }
            g_logits[p] = acc + bias[e];
        }
        __syncthreads();
        if (wid == 0) {
            int rem0 = cap, rem1 = cap;
            const float NEG = __int_as_float(0xff800000);
            for (int k = 0; k < TOPK; k++) {
                for (int b = 0; b < N_TOK; b++) {
                    float v0 = g_logits[(size_t)b * N_EXP + lane];
                    float v1 = g_logits[(size_t)b * N_EXP + 32 + lane];
                    float om = fmaxf(v0, v1);
                    #pragma unroll
                    for (int o = 16; o > 0; o >>= 1)
                        om = fmaxf(om, __shfl_xor_sync(0xffffffffu, om, o));
                    float os = __expf(v0 - om) + __expf(v1 - om);
                    #pragma unroll
                    for (int o = 16; o > 0; o >>= 1)
                        os += __shfl_xor_sync(0xffffffffu, os, o);
                    float m0 = (rem0 > 0) ? v0 : NEG; int i0 = lane;
                    float m1 = (rem1 > 0) ? v1 : NEG; int i1 = lane + 32;
                    float mv; int mi;
                    if (m1 > m0) { mv = m1; mi = i1; } else { mv = m0; mi = i0; }
                    #pragma unroll
                    for (int o = 16; o > 0; o >>= 1) {
                        float ov = __shfl_xor_sync(0xffffffffu, mv, o);
                        int   oi = __shfl_xor_sync(0xffffffffu, mi, o);
                        if (ov > mv || (ov == mv && oi < mi)) { mv = ov; mi = oi; }
                    }
                    int rsrc = (mi >= 32) ? rem1 : rem0;
                    int remch = __shfl_sync(0xffffffffu, rsrc, mi & 31);
                    bool ok = remch > 0;
                    if (ok && lane == (mi & 31)) { if (mi >= 32) rem1 -= 1; else rem0 -= 1; }
                    if (lane == 0) {
                        if (ok) {
                            float p = __expf(mv - om) / os;
                            out[b * TOPK + k] = (float)mi;
                            out[OUT_W_OFF + b * TOPK + k] = p;
                        } else {
                            out[b * TOPK + k] = -1.f;
                            out[OUT_W_OFF + b * TOPK + k] = 0.f;
                        }
                    }
                    __syncwarp();
                }
            }
            for (int b = lane; b < N_TOK; b += 32) {
                float w0 = out[OUT_W_OFF + b * TOPK + 0];
                float w1 = out[OUT_W_OFF + b * TOPK + 1];
                float w2 = out[OUT_W_OFF + b * TOPK + 2];
                float w3 = out[OUT_W_OFF + b * TOPK + 3];
                float ss = ((w0 + w1) + w2) + w3 + 1e-8f;
                out[OUT_W_OFF + b * TOPK + 0] = w0 / ss;
                out[OUT_W_OFF + b * TOPK + 1] = w1 / ss;
                out[OUT_W_OFF + b * TOPK + 2] = w2 / ss;
                out[OUT_W_OFF + b * TOPK + 3] = w3 / ss;
            }
        }
        return;
    }

    // ================= worker blocks: bf16 MMA GEMM + routing =================
    const int m0 = blockIdx.x * MT;

    if (tid < N_EXP) { s_bias[tid] = bias[tid]; s_cnt[tid] = 0; }
    if (tid == 0) s_qn = 0;

    // x loader: 8 thr/row, 8 floats each (one STS.128 per chunk)
    const int xrow = tid >> 3;
    const int xfo  = (tid & 7) * 8;
    const float4* xp = (const float4*)(x + (size_t)(m0 + xrow) * DIM + xfo);
    // W loader (bf16 src): 4 thr/row, 16 bf16 each = 2x cp.async 16B
    const int wrow = tid >> 2;
    const int wco  = (tid & 3) * 16;
    const __nv_bfloat16* wsrc = g_wbf + (size_t)wrow * DIM + wco;
    const uint32_t smw_base = (uint32_t)__cvta_generic_to_shared(smw);
    const uint32_t wdst = smw_base + (uint32_t)(wrow * 144 + wco * 2);

    // warp tile: 16 tokens x 16 experts
    const int wm = wid >> 2;
    const int wn = wid & 3;
    const int qr = lane >> 2, qc = lane & 3;

    float c[2][4];
    #pragma unroll
    for (int j = 0; j < 2; j++)
        #pragma unroll
        for (int i = 0; i < 4; i++) c[j][i] = 0.f;

    const uint32_t smx_base = (uint32_t)__cvta_generic_to_shared(smx);
    const uint32_t a_off = (uint32_t)((wm * 16 + (lane & 15)) * 144 + (lane >> 4) * 16);
    const uint32_t b_off = (uint32_t)((wn * 16 + ((lane >> 4) << 3) + (lane & 7)) * 144
                                      + ((lane >> 3) & 1) * 16);

    // prologue: x chunks 0,1 in regs; W chunk 0 via cp.async
    float4 rx[2][2];
    rx[0][0] = xp[0]; rx[0][1] = xp[1]; xp += KC / 4;
    rx[1][0] = xp[0]; rx[1][1] = xp[1]; xp += KC / 4;
    CP16(wdst, wsrc); CP16(wdst + 16, wsrc + 8);
    CP_COMMIT();
    wsrc += KC;

    for (int ci = 0; ci < NCHUNK; ci++) {
        const int buf = ci & 1;
        {
            uint4 v;
            v.x = bf2(rx[buf][0].x, rx[buf][0].y);
            v.y = bf2(rx[buf][0].z, rx[buf][0].w);
            v.z = bf2(rx[buf][1].x, rx[buf][1].y);
            v.w = bf2(rx[buf][1].z, rx[buf][1].w);
            *(uint4*)(smx + buf * XBYTES + xrow * 144 + xfo * 2) = v;
        }
        if (ci + 2 < NCHUNK) {
            rx[buf][0] = xp[0]; rx[buf][1] = xp[1]; xp += KC / 4;
        }
        CP_WAIT0();
        __syncthreads();
        if (ci + 1 < NCHUNK) {
            const uint32_t d = wdst + (buf ^ 1) * WBYTES;
            CP16(d, wsrc); CP16(d + 16, wsrc + 8);
            CP_COMMIT();
            wsrc += KC;
        }

        const uint32_t abase = smx_base + buf * XBYTES + a_off;
        const uint32_t bbase = smw_base + buf * WBYTES + b_off;
        #pragma unroll
        for (int kk = 0; kk < 4; kk++) {
            uint32_t a0, a1, a2, a3, b0, b1, b2, b3;
            asm volatile("ldmatrix.sync.aligned.m8n8.x4.shared.b16 {%0,%1,%2,%3}, [%4];"
                         : "=r"(a0), "=r"(a1), "=r"(a2), "=r"(a3)
                         : "r"(abase + kk * 32));
            asm volatile("ldmatrix.sync.aligned.m8n8.x4.shared.b16 {%0,%1,%2,%3}, [%4];"
                         : "=r"(b0), "=r"(b1), "=r"(b2), "=r"(b3)
                         : "r"(bbase + kk * 32));
            asm volatile(
                "mma.sync.aligned.m16n8k16.row.col.f32.bf16.bf16.f32 "
                "{%0,%1,%2,%3}, {%4,%5,%6,%7}, {%8,%9}, {%0,%1,%2,%3};"
                : "+f"(c[0][0]), "+f"(c[0][1]), "+f"(c[0][2]), "+f"(c[0][3])
                : "r"(a0), "r"(a1), "r"(a2), "r"(a3), "r"(b0), "r"(b1));
            asm volatile(
                "mma.sync.aligned.m16n8k16.row.col.f32.bf16.bf16.f32 "
                "{%0,%1,%2,%3}, {%4,%5,%6,%7}, {%8,%9}, {%0,%1,%2,%3};"
                : "+f"(c[1][0]), "+f"(c[1][1]), "+f"(c[1][2]), "+f"(c[1][3])
                : "r"(a0), "r"(a1), "r"(a2), "r"(a3), "r"(b2), "r"(b3));
        }
    }
    __syncthreads();

    // accumulators -> smem logits L[token][expert] (overlay smx)
    {
        float* L = (float*)smx;
        const int r0 = wm * 16 + qr;
        #pragma unroll
        for (int j = 0; j < 2; j++) {
            const int col = wn * 16 + j * 8 + qc * 2;
            L[r0 * L_STRIDE + col]           = c[j][0];
            L[r0 * L_STRIDE + col + 1]       = c[j][1];
            L[(r0 + 8) * L_STRIDE + col]     = c[j][2];
            L[(r0 + 8) * L_STRIDE + col + 1] = c[j][3];
        }
    }
    __syncthreads();

    // per-token epilogue: 2 threads per token, each scans 32 experts
    if (tid < 2 * MT) {
        const float* L = (const float*)smx;
        const int t    = tid >> 1;
        const int half = tid & 1;
        const int e0   = half * 32;
        const int b    = m0 + t;

        float v[32];
        #pragma unroll
        for (int j = 0; j < 32; j++) v[j] = L[t * L_STRIDE + e0 + j] + s_bias[e0 + j];

        float bm = v[0]; int bi = e0;
        #pragma unroll
        for (int j = 1; j < 32; j++)
            if (v[j] > bm) { bm = v[j]; bi = e0 + j; }

        float om = __shfl_xor_sync(0xffffffffu, bm, 1);
        int   oi = __shfl_xor_sync(0xffffffffu, bi, 1);
        if (om > bm || (om == bm && oi < bi)) { bm = om; bi = oi; }

        const float thr = bm - MARGIN;
        int ncl = 0;
        int cl[4];
        #pragma unroll
        for (int j = 0; j < 32; j++)
            if (v[j] >= thr) { if (ncl < 4) cl[ncl] = e0 + j; ncl++; }
        int nco = __shfl_xor_sync(0xffffffffu, ncl, 1);
        int nc = ncl + nco;
        if (ncl > 4 || nco > 4) nc = 255;    // overflow -> full recompute

        float s = 0.f;
        #pragma unroll
        for (int j = 0; j < 32; j++) s += __expf(v[j] - bm);
        s += __shfl_xor_sync(0xffffffffu, s, 1);

        if (half == 0) {
            const float w = 1.0f / (4.0f + 1e-8f * s);    // p/(4p+1e-8), p = 1/s
            ((float4*)(out + OUT_W_OFF))[b] = make_float4(w, w, w, w);
        }
        if (nc == 1) {
            if (half == 0) {
                float f = (float)bi;
                ((float4*)out)[b] = make_float4(f, f, f, f);
                atomicAdd(&s_cnt[bi], 1);
            }
        } else {
            int base = half ? ((nco <= 4) ? nco : 4) : 0;
            if (nc <= CAND_MAX) {
                for (int i = 0; i < ncl && i < 4; i++) s_cand[t][base + i] = cl[i];
            }
            if (half == 0) {
                s_nc[t] = nc;
                int qi = atomicAdd(&s_qn, 1);
                s_queue[qi] = t;
            }
        }
    }
    __syncthreads();

    // in-block exact fp32 refine for ambiguous tokens (one warp per token)
    {
        const int qn = s_qn;
        for (int q = wid; q < qn; q += 8) {
            const int t  = s_queue[q];
            const int b  = m0 + t;
            const int nc = s_nc[t];
            const int it = (nc > CAND_MAX) ? 64 : nc;
            const float4* xr = (const float4*)(x + (size_t)b * DIM);
            float bestv = -3.4e38f; int besti = 0;
            for (int i = 0; i < it; i++) {
                const int e = (nc > CAND_MAX) ? i : (s_cand[t][i] & 63);
                const float4* wr = (const float4*)(Wt + (size_t)e * DIM);
                float acc = 0.f;
                #pragma unroll 4
                for (int u = lane; u < DIM / 4; u += 32) {
                    float4 a = xr[u], cc = wr[u];
                    acc = fmaf(a.x, cc.x, acc); acc = fmaf(a.y, cc.y, acc);
                    acc = fmaf(a.z, cc.z, acc); acc = fmaf(a.w, cc.w, acc);
                }
                #pragma unroll
                for (int o = 16; o > 0; o >>= 1) acc += __shfl_xor_sync(0xffffffffu, acc, o);
                acc += s_bias[e];
                if (acc > bestv || (acc == bestv && e < besti)) { bestv = acc; besti = e; }
            }
            if (lane == 0) {
                float f = (float)besti;
                ((float4*)out)[b] = make_float4(f, f, f, f);
                atomicAdd(&s_cnt[besti], 1);
            }
        }
    }
    __syncthreads();
    if (tid < N_EXP) { int cv = s_cnt[tid]; if (cv) atomicAdd(&g_count[tid], cv); }
    __threadfence();
    __syncthreads();
    if (tid == 0) atomicAdd(&g_done, 1);
}

// ---------------- launch (2 kernels) ----------------
extern "C" void kernel_launch(void* const* d_in, const int* in_sizes, int n_in,
                              void* d_out, int out_size) {
    const float* x    = (const float*)d_in[0];
    const float* W    = (const float*)d_in[1];
    const float* bias = (const float*)d_in[2];
    const int*   tc   = (const int*)  d_in[3];
    float* out = (float*)d_out;

    wconv_kernel<<<N_EXP * DIM / (256 * 8), 256>>>(W);
    gemm_route_kernel<<<NWORK + 1, 256>>>(x, W, bias, tc, out);
}

// round 16
// speedup vs baseline: 2.4887x; 2.4887x over previous
#include <cuda_runtime.h>
#include <cuda_bf16.h>
#include <cstdint>
#include <math.h>

// CapacityAwareRouter: x(8192,2048) @ W(64,2048)^T + bias -> greedy capacity routing
#define N_TOK   8192
#define N_EXP   64
#define DIM     2048
#define TOPK    4
#define OUT_W_OFF (N_TOK * TOPK)
#define CAND_MAX 8
#define MARGIN  0.06f

// kernel A: 256 worker blocks + 1 spinner block; 256 threads; 32 tokens/block
#define MT       32
#define NWORK    (N_TOK / MT)        // 256
#define KC       64                  // bf16 K elems per chunk
#define NCHUNK   (DIM / KC)          // 32
#define L_STRIDE  65
#define XBYTES   (MT * 72 * 2)       // 4608
#define WBYTES   (N_EXP * 72 * 2)    // 9216

// ---------------- device scratch ----------------
__device__ float g_logits[N_TOK * N_EXP];                    // fallback only
__device__ int   g_count[N_EXP];
__device__ int   g_done;
__device__ __align__(16) __nv_bfloat16 g_wbf[N_EXP * DIM];   // 256 KB bf16 W

__device__ __forceinline__ uint32_t bf2(float lo, float hi) {
    uint32_t r;
    asm("cvt.rn.bf16x2.f32 %0, %2, %1;" : "=r"(r) : "f"(lo), "f"(hi));
    return r;
}
#define CP16(dst, src) \
    asm volatile("cp.async.cg.shared.global [%0], [%1], 16;" :: "r"(dst), "l"(src) : "memory")
#define CP_COMMIT() asm volatile("cp.async.commit_group;" ::: "memory")
#define CP_WAIT0()  asm volatile("cp.async.wait_group 0;" ::: "memory")

// ============ kernel W: fp32 W -> bf16 global ============
__global__ void wconv_kernel(const float* __restrict__ W) {
    const int i = (blockIdx.x * 256 + threadIdx.x) * 8;
    float4 a = *(const float4*)(W + i);
    float4 b = *(const float4*)(W + i + 4);
    uint4 v;
    v.x = bf2(a.x, a.y); v.y = bf2(a.z, a.w);
    v.z = bf2(b.x, b.y); v.w = bf2(b.z, b.w);
    *(uint4*)(g_wbf + i) = v;
}

// ============ kernel A: GEMM + routing + integrated fallback spinner ============
__global__ __launch_bounds__(256, 2)
void gemm_route_kernel(const float* __restrict__ x, const float* __restrict__ Wt,
                       const float* __restrict__ bias, const int* __restrict__ tc,
                       float* __restrict__ out) {
    __shared__ __align__(16) char smx[2 * XBYTES];   // x tiles (logits overlay later)
    __shared__ __align__(16) char smw[2 * WBYTES];   // W tiles
    __shared__ float s_bias[N_EXP];
    __shared__ int   s_cnt[N_EXP];
    __shared__ int   s_queue[MT];
    __shared__ int   s_nc[MT];
    __shared__ int   s_cand[MT][CAND_MAX];
    __shared__ int   s_qn;
    __shared__ int   s_bad;

    const int tid  = threadIdx.x;
    const int wid  = tid >> 5;
    const int lane = tid & 31;

    // ================= spinner block: capacity check + exact fallback =================
    if (blockIdx.x == NWORK) {
        if (tid == 0) {
            while (atomicAdd(&g_done, 0) < NWORK) { __nanosleep(200); }
            s_bad = 0;
        }
        __syncthreads();
        const int cap = tc[0] / TOPK;
        if (tid < N_EXP && TOPK * g_count[tid] > cap) atomicOr(&s_bad, 1);
        __syncthreads();
        const int bad = s_bad;
        // reset state for next graph replay
        if (tid < N_EXP) g_count[tid] = 0;
        if (tid == 0) g_done = 0;
        if (!bad) return;

        // ---- never-taken exact path: full fp32 logits + serial greedy ----
        for (int p = tid; p < N_TOK * N_EXP; p += 256) {
            const int b = p >> 6, e = p & 63;
            const float4* xr = (const float4*)(x + (size_t)b * DIM);
            const float4* wr = (const float4*)(Wt + (size_t)e * DIM);
            float acc = 0.f;
            for (int i = 0; i < DIM / 4; i++) {
                float4 a = xr[i], cc = wr[i];
                acc = fmaf(a.x, cc.x, acc); acc = fmaf(a.y, cc.y, acc);
                acc = fmaf(a.z, cc.z, acc); acc = fmaf(a.w, cc.w, acc);
            }
            g_logits[p] = acc + bias[e];
        }
        __syncthreads();
        if (wid == 0) {
            int rem0 = cap, rem1 = cap;
            const float NEG = __int_as_float(0xff800000);
            for (int k = 0; k < TOPK; k++) {
                for (int b = 0; b < N_TOK; b++) {
                    float v0 = g_logits[(size_t)b * N_EXP + lane];
                    float v1 = g_logits[(size_t)b * N_EXP + 32 + lane];
                    float om = fmaxf(v0, v1);
                    #pragma unroll
                    for (int o = 16; o > 0; o >>= 1)
                        om = fmaxf(om, __shfl_xor_sync(0xffffffffu, om, o));
                    float os = __expf(v0 - om) + __expf(v1 - om);
                    #pragma unroll
                    for (int o = 16; o > 0; o >>= 1)
                        os += __shfl_xor_sync(0xffffffffu, os, o);
                    float m0 = (rem0 > 0) ? v0 : NEG; int i0 = lane;
                    float m1 = (rem1 > 0) ? v1 : NEG; int i1 = lane + 32;
                    float mv; int mi;
                    if (m1 > m0) { mv = m1; mi = i1; } else { mv = m0; mi = i0; }
                    #pragma unroll
                    for (int o = 16; o > 0; o >>= 1) {
                        float ov = __shfl_xor_sync(0xffffffffu, mv, o);
                        int   oi = __shfl_xor_sync(0xffffffffu, mi, o);
                        if (ov > mv || (ov == mv && oi < mi)) { mv = ov; mi = oi; }
                    }
                    int rsrc = (mi >= 32) ? rem1 : rem0;
                    int remch = __shfl_sync(0xffffffffu, rsrc, mi & 31);
                    bool ok = remch > 0;
                    if (ok && lane == (mi & 31)) { if (mi >= 32) rem1 -= 1; else rem0 -= 1; }
                    if (lane == 0) {
                        if (ok) {
                            float p = __expf(mv - om) / os;
                            out[b * TOPK + k] = (float)mi;
                            out[OUT_W_OFF + b * TOPK + k] = p;
                        } else {
                            out[b * TOPK + k] = -1.f;
                            out[OUT_W_OFF + b * TOPK + k] = 0.f;
                        }
                    }
                    __syncwarp();
                }
            }
            for (int b = lane; b < N_TOK; b += 32) {
                float w0 = out[OUT_W_OFF + b * TOPK + 0];
                float w1 = out[OUT_W_OFF + b * TOPK + 1];
                float w2 = out[OUT_W_OFF + b * TOPK + 2];
                float w3 = out[OUT_W_OFF + b * TOPK + 3];
                float ss = ((w0 + w1) + w2) + w3 + 1e-8f;
                out[OUT_W_OFF + b * TOPK + 0] = w0 / ss;
                out[OUT_W_OFF + b * TOPK + 1] = w1 / ss;
                out[OUT_W_OFF + b * TOPK + 2] = w2 / ss;
                out[OUT_W_OFF + b * TOPK + 3] = w3 / ss;
            }
        }
        return;
    }

    // ================= worker blocks: bf16 MMA GEMM + routing =================
    const int m0 = blockIdx.x * MT;

    if (tid < N_EXP) { s_bias[tid] = bias[tid]; s_cnt[tid] = 0; }
    if (tid == 0) s_qn = 0;

    // x loader: 8 thr/row, 8 floats each (one STS.128 per chunk)
    const int xrow = tid >> 3;
    const int xfo  = (tid & 7) * 8;
    const float4* xp = (const float4*)(x + (size_t)(m0 + xrow) * DIM + xfo);
    // W loader (bf16 src): 4 thr/row, 16 bf16 each = 2x cp.async 16B
    const int wrow = tid >> 2;
    const int wco  = (tid & 3) * 16;
    const __nv_bfloat16* wsrc = g_wbf + (size_t)wrow * DIM + wco;
    const uint32_t smw_base = (uint32_t)__cvta_generic_to_shared(smw);
    const uint32_t wdst = smw_base + (uint32_t)(wrow * 144 + wco * 2);

    // warp tile: 16 tokens x 16 experts
    const int wm = wid >> 2;
    const int wn = wid & 3;
    const int qr = lane >> 2, qc = lane & 3;

    float c[2][4];
    #pragma unroll
    for (int j = 0; j < 2; j++)
        #pragma unroll
        for (int i = 0; i < 4; i++) c[j][i] = 0.f;

    const uint32_t smx_base = (uint32_t)__cvta_generic_to_shared(smx);
    const uint32_t a_off = (uint32_t)((wm * 16 + (lane & 15)) * 144 + (lane >> 4) * 16);
    const uint32_t b_off = (uint32_t)((wn * 16 + ((lane >> 4) << 3) + (lane & 7)) * 144
                                      + ((lane >> 3) & 1) * 16);

    // prologue: x chunks 0,1 in regs; W chunk 0 via cp.async
    float4 rx[2][2];
    rx[0][0] = xp[0]; rx[0][1] = xp[1]; xp += KC / 4;
    rx[1][0] = xp[0]; rx[1][1] = xp[1]; xp += KC / 4;
    CP16(wdst, wsrc); CP16(wdst + 16, wsrc + 8);
    CP_COMMIT();
    wsrc += KC;

    for (int ci = 0; ci < NCHUNK; ci++) {
        const int buf = ci & 1;
        {
            uint4 v;
            v.x = bf2(rx[buf][0].x, rx[buf][0].y);
            v.y = bf2(rx[buf][0].z, rx[buf][0].w);
            v.z = bf2(rx[buf][1].x, rx[buf][1].y);
            v.w = bf2(rx[buf][1].z, rx[buf][1].w);
            *(uint4*)(smx + buf * XBYTES + xrow * 144 + xfo * 2) = v;
        }
        if (ci + 2 < NCHUNK) {
            rx[buf][0] = xp[0]; rx[buf][1] = xp[1]; xp += KC / 4;
        }
        CP_WAIT0();
        __syncthreads();
        if (ci + 1 < NCHUNK) {
            const uint32_t d = wdst + (buf ^ 1) * WBYTES;
            CP16(d, wsrc); CP16(d + 16, wsrc + 8);
            CP_COMMIT();
            wsrc += KC;
        }

        const uint32_t abase = smx_base + buf * XBYTES + a_off;
        const uint32_t bbase = smw_base + buf * WBYTES + b_off;
        #pragma unroll
        for (int kk = 0; kk < 4; kk++) {
            uint32_t a0, a1, a2, a3, b0, b1, b2, b3;
            asm volatile("ldmatrix.sync.aligned.m8n8.x4.shared.b16 {%0,%1,%2,%3}, [%4];"
                         : "=r"(a0), "=r"(a1), "=r"(a2), "=r"(a3)
                         : "r"(abase + kk * 32));
            asm volatile("ldmatrix.sync.aligned.m8n8.x4.shared.b16 {%0,%1,%2,%3}, [%4];"
                         : "=r"(b0), "=r"(b1), "=r"(b2), "=r"(b3)
                         : "r"(bbase + kk * 32));
            asm volatile(
                "mma.sync.aligned.m16n8k16.row.col.f32.bf16.bf16.f32 "
                "{%0,%1,%2,%3}, {%4,%5,%6,%7}, {%8,%9}, {%0,%1,%2,%3};"
                : "+f"(c[0][0]), "+f"(c[0][1]), "+f"(c[0][2]), "+f"(c[0][3])
                : "r"(a0), "r"(a1), "r"(a2), "r"(a3), "r"(b0), "r"(b1));
            asm volatile(
                "mma.sync.aligned.m16n8k16.row.col.f32.bf16.bf16.f32 "
                "{%0,%1,%2,%3}, {%4,%5,%6,%7}, {%8,%9}, {%0,%1,%2,%3};"
                : "+f"(c[1][0]), "+f"(c[1][1]), "+f"(c[1][2]), "+f"(c[1][3])
                : "r"(a0), "r"(a1), "r"(a2), "r"(a3), "r"(b2), "r"(b3));
        }
    }
    __syncthreads();

    // accumulators -> smem logits L[token][expert] (overlay smx)
    {
        float* L = (float*)smx;
        const int r0 = wm * 16 + qr;
        #pragma unroll
        for (int j = 0; j < 2; j++) {
            const int col = wn * 16 + j * 8 + qc * 2;
            L[r0 * L_STRIDE + col]           = c[j][0];
            L[r0 * L_STRIDE + col + 1]       = c[j][1];
            L[(r0 + 8) * L_STRIDE + col]     = c[j][2];
            L[(r0 + 8) * L_STRIDE + col + 1] = c[j][3];
        }
    }
    __syncthreads();

    // per-token epilogue: 2 threads per token, each scans 32 experts
    if (tid < 2 * MT) {
        const float* L = (const float*)smx;
        const int t    = tid >> 1;
        const int half = tid & 1;
        const int e0   = half * 32;
        const int b    = m0 + t;

        float v[32];
        #pragma unroll
        for (int j = 0; j < 32; j++) v[j] = L[t * L_STRIDE + e0 + j] + s_bias[e0 + j];

        float bm = v[0]; int bi = e0;
        #pragma unroll
        for (int j = 1; j < 32; j++)
            if (v[j] > bm) { bm = v[j]; bi = e0 + j; }

        float om = __shfl_xor_sync(0xffffffffu, bm, 1);
        int   oi = __shfl_xor_sync(0xffffffffu, bi, 1);
        if (om > bm || (om == bm && oi < bi)) { bm = om; bi = oi; }

        const float thr = bm - MARGIN;
        int ncl = 0;
        int cl[4];
        #pragma unroll
        for (int j = 0; j < 32; j++)
            if (v[j] >= thr) { if (ncl < 4) cl[ncl] = e0 + j; ncl++; }
        int nco = __shfl_xor_sync(0xffffffffu, ncl, 1);
        int nc = ncl + nco;

        float s = 0.f;
        #pragma unroll
        for (int j = 0; j < 32; j++) s += __expf(v[j] - bm);
        s += __shfl_xor_sync(0xffffffffu, s, 1);

        if (half == 0) {
            const float w = 1.0f / (4.0f + 1e-8f * s);    // p/(4p+1e-8), p = 1/s
            ((float4*)(out + OUT_W_OFF))[b] = make_float4(w, w, w, w);
        }
        if (nc == 1) {
            if (half == 0) {
                float f = (float)bi;
                ((float4*)out)[b] = make_float4(f, f, f, f);
                atomicAdd(&s_cnt[bi], 1);
            }
        } else {
            int base = half ? ((nco <= 4) ? nco : 4) : 0;
            if (nc <= CAND_MAX) {
                for (int i = 0; i < ncl && i < 4; i++) s_cand[t][base + i] = cl[i];
            }
            if (half == 0) {
                s_nc[t] = nc;
                int qi = atomicAdd(&s_qn, 1);
                s_queue[qi] = t;
            }
        }
    }
    __syncthreads();

    // in-block exact fp32 refine for ambiguous tokens (one warp per token)
    {
        const int qn = s_qn;
        for (int q = wid; q < qn; q += 8) {
            const int t  = s_queue[q];
            const int b  = m0 + t;
            const int nc = s_nc[t];
            const int it = (nc > CAND_MAX) ? 64 : nc;
            const float4* xr = (const float4*)(x + (size_t)b * DIM);
            float bestv = -3.4e38f; int besti = 0;
            for (int i = 0; i < it; i++) {
                const int e = (nc > CAND_MAX) ? i : s_cand[t][i];
                const float4* wr = (const float4*)(Wt + (size_t)e * DIM);
                float acc = 0.f;
                #pragma unroll 4
                for (int u = lane; u < DIM / 4; u += 32) {
                    float4 a = xr[u], cc = wr[u];
                    acc = fmaf(a.x, cc.x, acc); acc = fmaf(a.y, cc.y, acc);
                    acc = fmaf(a.z, cc.z, acc); acc = fmaf(a.w, cc.w, acc);
                }
                #pragma unroll
                for (int o = 16; o > 0; o >>= 1) acc += __shfl_xor_sync(0xffffffffu, acc, o);
                acc += s_bias[e];
                if (acc > bestv || (acc == bestv && e < besti)) { bestv = acc; besti = e; }
            }
            if (lane == 0) {
                float f = (float)besti;
                ((float4*)out)[b] = make_float4(f, f, f, f);
                atomicAdd(&s_cnt[besti], 1);
            }
        }
    }
    __syncthreads();
    if (tid < N_EXP) { int cv = s_cnt[tid]; if (cv) atomicAdd(&g_count[tid], cv); }
    __threadfence();
    __syncthreads();
    if (tid == 0) atomicAdd(&g_done, 1);
}

// ---------------- launch (2 kernels) ----------------
extern "C" void kernel_launch(void* const* d_in, const int* in_sizes, int n_in,
                              void* d_out, int out_size) {
    const float* x    = (const float*)d_in[0];
    const float* W    = (const float*)d_in[1];
    const float* bias = (const float*)d_in[2];
    const int*   tc   = (const int*)  d_in[3];
    float* out = (float*)d_out;

    wconv_kernel<<<N_EXP * DIM / (256 * 8), 256>>>(W);
    gemm_route_kernel<<<NWORK + 1, 256>>>(x, W, bias, tc, out);
}

// round 17
// speedup vs baseline: 2.5649x; 1.0306x over previous
#include <cuda_runtime.h>
#include <cuda_bf16.h>
#include <cstdint>
#include <math.h>

// CapacityAwareRouter: x(8192,2048) @ W(64,2048)^T + bias -> greedy capacity routing
#define N_TOK   8192
#define N_EXP   64
#define DIM     2048
#define TOPK    4
#define OUT_W_OFF (N_TOK * TOPK)
#define CAND_MAX 8
#define MARGIN  0.06f

// 256 worker blocks + 1 spinner; 256 threads; 32 tokens/block
#define MT       32
#define NWORK    (N_TOK / MT)        // 256
#define KC       64                  // K elems per chunk
#define NCHUNK   (DIM / KC)          // 32
#define NPAIR    (NCHUNK / 2)        // 16 sync rounds
#define L_STRIDE 65
#define XBYTES   (MT * 72 * 2)       // 4608 per chunk-slot
#define WBYTES   (N_EXP * 72 * 2)    // 9216 per chunk-slot
// dynamic smem: 4 x slots + 4 W slots
#define SM_X     0
#define SM_W     (4 * XBYTES)              // 18432
#define SM_TOTAL (SM_W + 4 * WBYTES)       // 55296

// ---------------- device scratch ----------------
__device__ float g_logits[N_TOK * N_EXP];                    // fallback only
__device__ int   g_count[N_EXP];
__device__ int   g_done;
__device__ __align__(16) __nv_bfloat16 g_wbf[N_EXP * DIM];   // 256 KB bf16 W

__device__ __forceinline__ uint32_t bf2(float lo, float hi) {
    uint32_t r;
    asm("cvt.rn.bf16x2.f32 %0, %2, %1;" : "=r"(r) : "f"(lo), "f"(hi));
    return r;
}
#define CP16(dst, src) \
    asm volatile("cp.async.cg.shared.global [%0], [%1], 16;" :: "r"(dst), "l"(src) : "memory")
#define CP_COMMIT() asm volatile("cp.async.commit_group;" ::: "memory")
#define CP_WAIT0()  asm volatile("cp.async.wait_group 0;" ::: "memory")

// ============ kernel 1: fp32 W -> bf16 global ============
__global__ void wconv_kernel(const float* __restrict__ W) {
    const int i = (blockIdx.x * 256 + threadIdx.x) * 8;
    float4 a = *(const float4*)(W + i);
    float4 b = *(const float4*)(W + i + 4);
    uint4 v;
    v.x = bf2(a.x, a.y); v.y = bf2(a.z, a.w);
    v.z = bf2(b.x, b.y); v.w = bf2(b.z, b.w);
    *(uint4*)(g_wbf + i) = v;
}

// ============ kernel 2: GEMM + routing + integrated fallback spinner ============
__global__ __launch_bounds__(256, 2)
void gemm_route_kernel(const float* __restrict__ x, const float* __restrict__ Wt,
                       const float* __restrict__ bias, const int* __restrict__ tc,
                       float* __restrict__ out) {
    extern __shared__ __align__(16) char dsm[];
    __shared__ float s_bias[N_EXP];
    __shared__ int   s_cnt[N_EXP];
    __shared__ int   s_queue[MT];
    __shared__ int   s_nc[MT];
    __shared__ int   s_cand[MT][CAND_MAX];
    __shared__ int   s_qn;
    __shared__ int   s_bad;

    const int tid  = threadIdx.x;
    const int wid  = tid >> 5;
    const int lane = tid & 31;

    // ================= spinner block: capacity check + exact fallback =================
    if (blockIdx.x == NWORK) {
        if (tid == 0) {
            while (atomicAdd(&g_done, 0) < NWORK) { __nanosleep(200); }
            s_bad = 0;
        }
        __syncthreads();
        const int cap = tc[0] / TOPK;
        if (tid < N_EXP && TOPK * g_count[tid] > cap) atomicOr(&s_bad, 1);
        __syncthreads();
        const int bad = s_bad;
        if (tid < N_EXP) g_count[tid] = 0;   // reset for next replay
        if (tid == 0) g_done = 0;
        if (!bad) return;

        // ---- never-taken exact path: full fp32 logits + serial greedy ----
        for (int p = tid; p < N_TOK * N_EXP; p += 256) {
            const int b = p >> 6, e = p & 63;
            const float4* xr = (const float4*)(x + (size_t)b * DIM);
            const float4* wr = (const float4*)(Wt + (size_t)e * DIM);
            float acc = 0.f;
            for (int i = 0; i < DIM / 4; i++) {
                float4 a = xr[i], cc = wr[i];
                acc = fmaf(a.x, cc.x, acc); acc = fmaf(a.y, cc.y, acc);
                acc = fmaf(a.z, cc.z, acc); acc = fmaf(a.w, cc.w, acc);
            }
            g_logits[p] = acc + bias[e];
        }
        __syncthreads();
        if (wid == 0) {
            int rem0 = cap, rem1 = cap;
            const float NEG = __int_as_float(0xff800000);
            for (int k = 0; k < TOPK; k++) {
                for (int b = 0; b < N_TOK; b++) {
                    float v0 = g_logits[(size_t)b * N_EXP + lane];
                    float v1 = g_logits[(size_t)b * N_EXP + 32 + lane];
                    float om = fmaxf(v0, v1);
                    #pragma unroll
                    for (int o = 16; o > 0; o >>= 1)
                        om = fmaxf(om, __shfl_xor_sync(0xffffffffu, om, o));
                    float os = __expf(v0 - om) + __expf(v1 - om);
                    #pragma unroll
                    for (int o = 16; o > 0; o >>= 1)
                        os += __shfl_xor_sync(0xffffffffu, os, o);
                    float m0v = (rem0 > 0) ? v0 : NEG; int i0 = lane;
                    float m1v = (rem1 > 0) ? v1 : NEG; int i1 = lane + 32;
                    float mv; int mi;
                    if (m1v > m0v) { mv = m1v; mi = i1; } else { mv = m0v; mi = i0; }
                    #pragma unroll
                    for (int o = 16; o > 0; o >>= 1) {
                        float ov = __shfl_xor_sync(0xffffffffu, mv, o);
                        int   oi = __shfl_xor_sync(0xffffffffu, mi, o);
                        if (ov > mv || (ov == mv && oi < mi)) { mv = ov; mi = oi; }
                    }
                    int rsrc = (mi >= 32) ? rem1 : rem0;
                    int remch = __shfl_sync(0xffffffffu, rsrc, mi & 31);
                    bool ok = remch > 0;
                    if (ok && lane == (mi & 31)) { if (mi >= 32) rem1 -= 1; else rem0 -= 1; }
                    if (lane == 0) {
                        if (ok) {
                            float p = __expf(mv - om) / os;
                            out[b * TOPK + k] = (float)mi;
                            out[OUT_W_OFF + b * TOPK + k] = p;
                        } else {
                            out[b * TOPK + k] = -1.f;
                            out[OUT_W_OFF + b * TOPK + k] = 0.f;
                        }
                    }
                    __syncwarp();
                }
            }
            for (int b = lane; b < N_TOK; b += 32) {
                float w0 = out[OUT_W_OFF + b * TOPK + 0];
                float w1 = out[OUT_W_OFF + b * TOPK + 1];
                float w2 = out[OUT_W_OFF + b * TOPK + 2];
                float w3 = out[OUT_W_OFF + b * TOPK + 3];
                float ss = ((w0 + w1) + w2) + w3 + 1e-8f;
                out[OUT_W_OFF + b * TOPK + 0] = w0 / ss;
                out[OUT_W_OFF + b * TOPK + 1] = w1 / ss;
                out[OUT_W_OFF + b * TOPK + 2] = w2 / ss;
                out[OUT_W_OFF + b * TOPK + 3] = w3 / ss;
            }
        }
        return;
    }

    // ================= worker blocks: bf16 MMA GEMM, barrier per chunk-pair =================
    const int m0 = blockIdx.x * MT;

    if (tid < N_EXP) { s_bias[tid] = bias[tid]; s_cnt[tid] = 0; }
    if (tid == 0) s_qn = 0;

    const uint32_t smb = (uint32_t)__cvta_generic_to_shared(dsm);

    // x loader: 8 thr/row, 8 floats each per chunk (one STS.128 per chunk)
    const int xrow = tid >> 3;
    const int xfo  = (tid & 7) * 8;
    const float4* xp = (const float4*)(x + (size_t)(m0 + xrow) * DIM + xfo);
    // W loader (bf16 src): 4 thr/row, 16 bf16 each per chunk = 2x cp.async 16B
    const int wrow = tid >> 2;
    const int wco  = (tid & 3) * 16;
    const __nv_bfloat16* wsrc = g_wbf + (size_t)wrow * DIM + wco;
    const uint32_t wd = smb + SM_W + (uint32_t)(wrow * 144 + wco * 2);

    // warp tile: 16 tokens x 16 experts (proven mapping)
    const int wm = wid >> 2;
    const int wn = wid & 3;
    const int qr = lane >> 2, qc = lane & 3;
    const uint32_t a_off = (uint32_t)((wm * 16 + (lane & 15)) * 144 + (lane >> 4) * 16);
    const uint32_t b_off = (uint32_t)((wn * 16 + ((lane >> 4) << 3) + (lane & 7)) * 144
                                      + ((lane >> 3) & 1) * 16);

    float c[2][4];
    #pragma unroll
    for (int j = 0; j < 2; j++)
        #pragma unroll
        for (int i = 0; i < 4; i++) c[j][i] = 0.f;

    // prologue: x pair0 (chunks 0,1) in regs; W pair0 via cp.async (one group)
    float4 rx[2][2];
    rx[0][0] = xp[0]; rx[0][1] = xp[1]; xp += KC / 4;
    rx[1][0] = xp[0]; rx[1][1] = xp[1]; xp += KC / 4;
    CP16(wd, wsrc); CP16(wd + 16, wsrc + 8);
    wsrc += KC;
    CP16(wd + WBYTES, wsrc); CP16(wd + WBYTES + 16, wsrc + 8);
    CP_COMMIT();
    wsrc += KC;

    for (int p = 0; p < NPAIR; p++) {
        const int pb = p & 1;                 // pair buffer: slots pb*2, pb*2+1
        // STS x chunks (2p, 2p+1) from regs
        #pragma unroll
        for (int cth = 0; cth < 2; cth++) {
            uint4 v;
            v.x = bf2(rx[cth][0].x, rx[cth][0].y);
            v.y = bf2(rx[cth][0].z, rx[cth][0].w);
            v.z = bf2(rx[cth][1].x, rx[cth][1].y);
            v.w = bf2(rx[cth][1].z, rx[cth][1].w);
            *(uint4*)(dsm + SM_X + (pb * 2 + cth) * XBYTES + xrow * 144 + xfo * 2) = v;
        }
        // LDG next pair
        if (p + 1 < NPAIR) {
            rx[0][0] = xp[0]; rx[0][1] = xp[1]; xp += KC / 4;
            rx[1][0] = xp[0]; rx[1][1] = xp[1]; xp += KC / 4;
        }
        CP_WAIT0();            // W pair p landed
        __syncthreads();       // x/W pair p visible; compute(pair p-1) drained
        if (p + 1 < NPAIR) {   // issue W pair p+1 into slots freed by pair p-1
            const uint32_t d = wd + ((pb ^ 1) * 2) * WBYTES;
            CP16(d, wsrc); CP16(d + 16, wsrc + 8);
            wsrc += KC;
            CP16(d + WBYTES, wsrc); CP16(d + WBYTES + 16, wsrc + 8);
            CP_COMMIT();
            wsrc += KC;
        }

        // compute both chunks of pair p
        #pragma unroll
        for (int cth = 0; cth < 2; cth++) {
            const uint32_t abase = smb + SM_X + (pb * 2 + cth) * XBYTES + a_off;
            const uint32_t bbase = smb + SM_W + (pb * 2 + cth) * WBYTES + b_off;
            #pragma unroll
            for (int kk = 0; kk < 4; kk++) {
                uint32_t a0, a1, a2, a3, b0, b1, b2, b3;
                asm volatile("ldmatrix.sync.aligned.m8n8.x4.shared.b16 {%0,%1,%2,%3}, [%4];"
                             : "=r"(a0), "=r"(a1), "=r"(a2), "=r"(a3)
                             : "r"(abase + kk * 32));
                asm volatile("ldmatrix.sync.aligned.m8n8.x4.shared.b16 {%0,%1,%2,%3}, [%4];"
                             : "=r"(b0), "=r"(b1), "=r"(b2), "=r"(b3)
                             : "r"(bbase + kk * 32));
                asm volatile(
                    "mma.sync.aligned.m16n8k16.row.col.f32.bf16.bf16.f32 "
                    "{%0,%1,%2,%3}, {%4,%5,%6,%7}, {%8,%9}, {%0,%1,%2,%3};"
                    : "+f"(c[0][0]), "+f"(c[0][1]), "+f"(c[0][2]), "+f"(c[0][3])
                    : "r"(a0), "r"(a1), "r"(a2), "r"(a3), "r"(b0), "r"(b1));
                asm volatile(
                    "mma.sync.aligned.m16n8k16.row.col.f32.bf16.bf16.f32 "
                    "{%0,%1,%2,%3}, {%4,%5,%6,%7}, {%8,%9}, {%0,%1,%2,%3};"
                    : "+f"(c[1][0]), "+f"(c[1][1]), "+f"(c[1][2]), "+f"(c[1][3])
                    : "r"(a0), "r"(a1), "r"(a2), "r"(a3), "r"(b2), "r"(b3));
            }
        }
    }
    __syncthreads();   // compute done everywhere before overlaying dsm with logits

    // accumulators -> smem logits L[token][expert] (overlay dsm)
    {
        float* L = (float*)dsm;
        const int r0 = wm * 16 + qr;
        #pragma unroll
        for (int j = 0; j < 2; j++) {
            const int col = wn * 16 + j * 8 + qc * 2;
            L[r0 * L_STRIDE + col]           = c[j][0];
            L[r0 * L_STRIDE + col + 1]       = c[j][1];
            L[(r0 + 8) * L_STRIDE + col]     = c[j][2];
            L[(r0 + 8) * L_STRIDE + col + 1] = c[j][3];
        }
    }
    __syncthreads();

    // per-token epilogue: 2 threads per token, each scans 32 experts
    if (tid < 2 * MT) {
        const float* L = (const float*)dsm;
        const int t    = tid >> 1;
        const int half = tid & 1;
        const int e0   = half * 32;
        const int b    = m0 + t;

        float v[32];
        #pragma unroll
        for (int j = 0; j < 32; j++) v[j] = L[t * L_STRIDE + e0 + j] + s_bias[e0 + j];

        float bm = v[0]; int bi = e0;
        #pragma unroll
        for (int j = 1; j < 32; j++)
            if (v[j] > bm) { bm = v[j]; bi = e0 + j; }

        float om = __shfl_xor_sync(0xffffffffu, bm, 1);
        int   oi = __shfl_xor_sync(0xffffffffu, bi, 1);
        if (om > bm || (om == bm && oi < bi)) { bm = om; bi = oi; }

        const float thr = bm - MARGIN;
        int ncl = 0;
        int cl[4];
        #pragma unroll
        for (int j = 0; j < 32; j++)
            if (v[j] >= thr) { if (ncl < 4) cl[ncl] = e0 + j; ncl++; }
        int nco = __shfl_xor_sync(0xffffffffu, ncl, 1);
        int nc = ncl + nco;

        float s = 0.f;
        #pragma unroll
        for (int j = 0; j < 32; j++) s += __expf(v[j] - bm);
        s += __shfl_xor_sync(0xffffffffu, s, 1);

        if (half == 0) {
            const float w = 1.0f / (4.0f + 1e-8f * s);    // p/(4p+1e-8), p = 1/s
            ((float4*)(out + OUT_W_OFF))[b] = make_float4(w, w, w, w);
        }
        if (nc == 1) {
            if (half == 0) {
                float f = (float)bi;
                ((float4*)out)[b] = make_float4(f, f, f, f);
                atomicAdd(&s_cnt[bi], 1);
            }
        } else {
            int base = half ? ((nco <= 4) ? nco : 4) : 0;
            if (nc <= CAND_MAX) {
                for (int i = 0; i < ncl && i < 4; i++) s_cand[t][base + i] = cl[i];
            }
            if (half == 0) {
                s_nc[t] = nc;
                int qi = atomicAdd(&s_qn, 1);
                s_queue[qi] = t;
            }
        }
    }
    __syncthreads();

    // in-block exact fp32 refine for ambiguous tokens (one warp per token)
    {
        const int qn = s_qn;
        for (int q = wid; q < qn; q += 8) {
            const int t  = s_queue[q];
            const int b  = m0 + t;
            const int nc = s_nc[t];
            const int it = (nc > CAND_MAX) ? 64 : nc;
            const float4* xr = (const float4*)(x + (size_t)b * DIM);
            float bestv = -3.4e38f; int besti = 0;
            for (int i = 0; i < it; i++) {
                const int e = (nc > CAND_MAX) ? i : s_cand[t][i];
                const float4* wr = (const float4*)(Wt + (size_t)e * DIM);
                float acc = 0.f;
                #pragma unroll 4
                for (int u = lane; u < DIM / 4; u += 32) {
                    float4 a = xr[u], cc = wr[u];
                    acc = fmaf(a.x, cc.x, acc); acc = fmaf(a.y, cc.y, acc);
                    acc = fmaf(a.z, cc.z, acc); acc = fmaf(a.w, cc.w, acc);
                }
                #pragma unroll
                for (int o = 16; o > 0; o >>= 1) acc += __shfl_xor_sync(0xffffffffu, acc, o);
                acc += s_bias[e];
                if (acc > bestv || (acc == bestv && e < besti)) { bestv = acc; besti = e; }
            }
            if (lane == 0) {
                float f = (float)besti;
                ((float4*)out)[b] = make_float4(f, f, f, f);
                atomicAdd(&s_cnt[besti], 1);
            }
        }
    }
    __syncthreads();
    if (tid < N_EXP) { int cv = s_cnt[tid]; if (cv) atomicAdd(&g_count[tid], cv); }
    __threadfence();
    __syncthreads();
    if (tid == 0) atomicAdd(&g_done, 1);
}

// ---------------- launch (2 kernels) ----------------
extern "C" void kernel_launch(void* const* d_in, const int* in_sizes, int n_in,
                              void* d_out, int out_size) {
    const float* x    = (const float*)d_in[0];
    const float* W    = (const float*)d_in[1];
    const float* bias = (const float*)d_in[2];
    const int*   tc   = (const int*)  d_in[3];
    float* out = (float*)d_out;

    static int configured = 0;
    if (!configured) {
        cudaFuncSetAttribute(gemm_route_kernel,
                             cudaFuncAttributeMaxDynamicSharedMemorySize, SM_TOTAL);
        configured = 1;
    }
    wconv_kernel<<<N_EXP * DIM / (256 * 8), 256>>>(W);
    gemm_route_kernel<<<NWORK + 1, 256, SM_TOTAL>>>(x, W, bias, tc, out);
}